// round 12
// baseline (speedup 1.0000x reference)
#include <cuda_runtime.h>
#include <math.h>

#define BATCH 8
#define NPTS  8192
#define NSLOT 16                     // 8 batches x 2 clouds
#define TOTPTS (NSLOT * NPTS)        // 131072
#define G 32
#define NC (G * G * G)               // 32768 cells per grid
#define NCT (NSLOT * NC)             // 524288 cells total
#define NTILE 512                    // scan tiles (1024 cells each)
#define NCHUNK 4096                  // query warp-chunks (32 queries each)
#define LOB  (-5.5f)
#define HCELL (11.0f / G)
#define INVH  (G / 11.0f)
#define EPSF 1e-10f

#define FLG_AGG 0x40000000u
#define FLG_INC 0x80000000u
#define VALMASK 0x3FFFFFFFu

// ---- static scratch (no allocation; zero-initialized at module load) ------
__device__ float4   g_pk[TOTPTS];      // packed points, original order
__device__ float4   g_sorted[TOTPTS];  // points sorted by cell (global CSR)
__device__ int      g_cell[TOTPTS];    // flat cell id per point
__device__ int      g_cnt[NCT];        // histogram (self-cleaned by scan)
__device__ int      g_start[NCT + 1];  // CSR starts + sentinel
__device__ int      g_cursor[NCT];     // scatter cursors
__device__ int      g_ticket;          // scan tile ticket (reset by final)
__device__ unsigned g_tstate[NTILE];   // lookback states (reset by final)
__device__ float    g_wpart[NCHUNK];   // per-warp-chunk partial sums

// ---------------------------------------------------------------------------
// Pack points, compute cells, histogram.
// ---------------------------------------------------------------------------
__global__ void assign_kernel(const float* __restrict__ x,
                              const float* __restrict__ y) {
    int t = blockIdx.x * 256 + threadIdx.x;
    int slot = t >> 13, i = t & (NPTS - 1);
    int b = slot >> 1;
    const float* src = (slot & 1) ? y : x;
    const float* p = src + ((size_t)b * NPTS + i) * 3;
    float px = p[0], py = p[1], pz = p[2];
    int cx = min(G - 1, max(0, (int)((px - LOB) * INVH)));
    int cy = min(G - 1, max(0, (int)((py - LOB) * INVH)));
    int cz = min(G - 1, max(0, (int)((pz - LOB) * INVH)));
    int c = slot * NC + ((cz * G + cy) * G + cx);
    g_pk[t] = make_float4(px, py, pz, 0.0f);
    g_cell[t] = c;
    atomicAdd(&g_cnt[c], 1);
}

// ---------------------------------------------------------------------------
// Single-pass exclusive scan of g_cnt (decoupled lookback, ticket-ordered).
// Zeroes g_cnt for the next graph replay; fills g_start and g_cursor.
// ---------------------------------------------------------------------------
__global__ void __launch_bounds__(1024) scan_kernel() {
    __shared__ int tile_s, exc_s;
    __shared__ int ws[32];
    int tid = threadIdx.x, lane = tid & 31, w = tid >> 5;

    if (tid == 0) tile_s = atomicAdd(&g_ticket, 1);
    __syncthreads();
    const int tile = tile_s;
    const int i = tile * 1024 + tid;

    int v = g_cnt[i];
    g_cnt[i] = 0;                                  // self-clean for next call

    int s = v;
    #pragma unroll
    for (int o = 1; o < 32; o <<= 1) {
        int t = __shfl_up_sync(0xffffffffu, s, o);
        if (lane >= o) s += t;
    }
    if (lane == 31) ws[w] = s;
    __syncthreads();
    if (w == 0) {
        int t = ws[lane];
        #pragma unroll
        for (int o = 1; o < 32; o <<= 1) {
            int u = __shfl_up_sync(0xffffffffu, t, o);
            if (lane >= o) t += u;
        }
        ws[lane] = t;
    }
    __syncthreads();
    int local_exc = ((w > 0) ? ws[w - 1] : 0) + s - v;
    int total = ws[31];

    if (tid == 0) {
        if (tile == 0) {
            __threadfence();
            atomicExch(&g_tstate[0], FLG_INC | (unsigned)total);
            exc_s = 0;
        } else {
            __threadfence();
            atomicExch(&g_tstate[tile], FLG_AGG | (unsigned)total);
            int exc = 0, j = tile - 1;
            while (true) {
                unsigned st = atomicAdd(&g_tstate[j], 0u);
                if (st & FLG_INC) { exc += (int)(st & VALMASK); break; }
                if (st & FLG_AGG) { exc += (int)(st & VALMASK); j--; }
            }
            __threadfence();
            atomicExch(&g_tstate[tile], FLG_INC | (unsigned)(exc + total));
            exc_s = exc;
        }
    }
    __syncthreads();
    int e = exc_s + local_exc;
    g_start[i]  = e;
    g_cursor[i] = e;
    if (i == 0) g_start[NCT] = TOTPTS;
}

__global__ void scatter_kernel() {
    int t = blockIdx.x * 256 + threadIdx.x;
    int pos = atomicAdd(&g_cursor[g_cell[t]], 1);
    g_sorted[pos] = g_pk[t];
}

// ---------------------------------------------------------------------------
// Candidate scan of a contiguous CSR range with x2 unroll / dual accumulators.
// ---------------------------------------------------------------------------
__device__ __forceinline__ void scan_range(int s, int e, float4 qp,
                                           float& b0, float& b1) {
    int j = s;
    for (; j + 2 <= e; j += 2) {
        float4 p0 = g_sorted[j];
        float4 p1 = g_sorted[j + 1];
        float dx0 = qp.x - p0.x, dy0 = qp.y - p0.y, dz0 = qp.z - p0.z;
        float dx1 = qp.x - p1.x, dy1 = qp.y - p1.y, dz1 = qp.z - p1.z;
        b0 = fminf(b0, fmaf(dx0, dx0, fmaf(dy0, dy0, dz0 * dz0)));
        b1 = fminf(b1, fmaf(dx1, dx1, fmaf(dy1, dy1, dz1 * dz1)));
    }
    if (j < e) {
        float4 p = g_sorted[j];
        float dx = qp.x - p.x, dy = qp.y - p.y, dz = qp.z - p.z;
        b0 = fminf(b0, fmaf(dx, dx, fmaf(dy, dy, dz * dz)));
    }
}

__device__ __forceinline__ void scan_cells(int c0, int width, float4 qp,
                                           float& best) {
    int s = g_start[c0];
    int e = g_start[c0 + width];
    float b0 = best, b1 = 1e30f;
    scan_range(s, e, qp, b0, b1);
    best = fminf(b0, b1);
}

// ---------------------------------------------------------------------------
// Exact NN via expanding Chebyshev shells over the CSR grid.
// Queries in cell-sorted IDENTITY order (warp lanes spatially adjacent ->
// broadcast L1 hits; adjacent warps share L1 working set). r=1 ball issues
// all 18 row-range loads up front (full MLP), then scans rows with a x2
// unrolled dual-accumulator loop. Shells r>=2 are the rare path.
// Correctness: after ball r is scanned, any unscanned point is >= r*HCELL
// away (per-axis clamped assignment is 1-Lipschitz); stop when
// best <= (r*h)^2; worst case r=G => full scan => exact.
// ---------------------------------------------------------------------------
__global__ void __launch_bounds__(128) query_kernel() {
    int qid = blockIdx.x * 128 + threadIdx.x;          // [0, 131072)
    int lane = threadIdx.x & 31;
    int d = qid >> 16;
    int q = qid & 65535;
    int b = q >> 13;
    int i = q & (NPTS - 1);
    int qslot  = b * 2 + d;
    int dbslot = b * 2 + (1 - d);

    float4 qp = g_sorted[qslot * NPTS + i];            // cell-sorted query
    int cx = min(G - 1, max(0, (int)((qp.x - LOB) * INVH)));
    int cy = min(G - 1, max(0, (int)((qp.y - LOB) * INVH)));
    int cz = min(G - 1, max(0, (int)((qp.z - LOB) * INVH)));
    const int base = dbslot * NC;

    // ---- Ball r=1: prefetch all 9 row ranges (18 independent loads) ------
    int rs[9], re[9];
    const int x0 = max(cx - 1, 0), x1 = min(cx + 1, G - 1);
    #pragma unroll
    for (int k = 0; k < 9; k++) {
        int z = cz + (k / 3) - 1;
        int y = cy + (k % 3) - 1;
        bool valid = ((unsigned)z < G) & ((unsigned)y < G);
        int row = base + (z * G + y) * G;
        rs[k] = valid ? g_start[row + x0]     : 0;
        re[k] = valid ? g_start[row + x1 + 1] : 0;
    }

    float b0 = 1e30f, b1 = 1e30f;
    #pragma unroll
    for (int k = 0; k < 9; k++)
        scan_range(rs[k], re[k], qp, b0, b1);
    float best = fminf(b0, b1);

    // ---- Expanding shells (rare path) -------------------------------------
    int r = 1;
    while (!(best <= (r * HCELL) * (r * HCELL) * 0.9999f) && r < G) {
        r++;
        for (int dz = -r; dz <= r; dz++) {
            int z = cz + dz;
            if ((unsigned)z >= G) continue;
            int adz = (dz < 0) ? -dz : dz;
            for (int dy = -r; dy <= r; dy++) {
                int y = cy + dy;
                if ((unsigned)y >= G) continue;
                int ady = (dy < 0) ? -dy : dy;
                int rowbase = base + (z * G + y) * G;
                if (adz == r || ady == r) {
                    int xa = max(cx - r, 0), xb = min(cx + r, G - 1);
                    scan_cells(rowbase + xa, xb - xa + 1, qp, best);
                } else {
                    int xa = cx - r;
                    if (xa >= 0) scan_cells(rowbase + xa, 1, qp, best);
                    int xb = cx + r;
                    if (xb < G) scan_cells(rowbase + xb, 1, qp, best);
                }
            }
        }
    }

    float dist = sqrtf(best + EPSF);
    #pragma unroll
    for (int o = 16; o > 0; o >>= 1)
        dist += __shfl_down_sync(0xffffffffu, dist, o);
    if (lane == 0) g_wpart[qid >> 5] = dist;           // identity chunk order
}

// ---------------------------------------------------------------------------
// Fold 4096 chunk-partials -> 16 (d,b) sums -> max over d -> mean -> total.
// Chunk c: group = c>>8 (d = grp>>3, b = grp&7). Also resets scan state.
// ---------------------------------------------------------------------------
__global__ void __launch_bounds__(512) final_kernel(float* __restrict__ out) {
    int t = threadIdx.x, grp = t >> 5, lane = t & 31;
    g_tstate[t] = 0u;
    if (t == 0) g_ticket = 0;

    float s = 0.0f;
    #pragma unroll
    for (int k = 0; k < 8; k++)
        s += g_wpart[grp * 256 + k * 32 + lane];
    #pragma unroll
    for (int o = 16; o > 0; o >>= 1)
        s += __shfl_down_sync(0xffffffffu, s, o);

    __shared__ float ss[16];
    if (lane == 0) ss[grp] = s;
    __syncthreads();
    if (t == 0) {
        float tot = 0.0f;
        #pragma unroll
        for (int bb = 0; bb < BATCH; bb++)
            tot += fmaxf(ss[bb], ss[8 + bb]) * (1.0f / NPTS);
        out[0] = tot;
    }
}

// ---------------------------------------------------------------------------
extern "C" void kernel_launch(void* const* d_in, const int* in_sizes, int n_in,
                              void* d_out, int out_size) {
    const float* x = (const float*)d_in[0];
    const float* y = (const float*)d_in[1];
    float* out = (float*)d_out;

    assign_kernel<<<TOTPTS / 256, 256>>>(x, y);
    scan_kernel<<<NTILE, 1024>>>();
    scatter_kernel<<<TOTPTS / 256, 256>>>();
    query_kernel<<<TOTPTS / 128, 128>>>();
    final_kernel<<<1, 512>>>(out);
}

// round 15
// speedup vs baseline: 1.0655x; 1.0655x over previous
#include <cuda_runtime.h>
#include <math.h>

#define BATCH 8
#define NPTS  8192
#define NSLOT 16                     // 8 batches x 2 clouds
#define TOTPTS (NSLOT * NPTS)        // 131072
#define G 32
#define NC (G * G * G)               // 32768 cells per grid
#define NCT (NSLOT * NC)             // 524288 cells total
#define NTILE 512                    // scan tiles (1024 cells each)
#define NCHUNK2 8192                 // query chunks (16 queries each)
#define QGRID 592                    // query blocks (work-stealing)
#define LOB  (-5.5f)
#define HCELL (11.0f / G)
#define INVH  (G / 11.0f)
#define EPSF 1e-10f

#define FLG_AGG 0x40000000u
#define FLG_INC 0x80000000u
#define VALMASK 0x3FFFFFFFu

// ---- static scratch (no allocation; zero-initialized at module load) ------
__device__ float4   g_pk[TOTPTS];      // packed points, original order
__device__ float4   g_sorted[TOTPTS];  // points sorted by cell (global CSR)
__device__ int      g_cell[TOTPTS];    // flat cell id per point
__device__ int      g_cnt[NCT];        // histogram (self-cleaned by scan)
__device__ int      g_start[NCT + 1];  // CSR starts + sentinel
__device__ int      g_cursor[NCT];     // scatter cursors
__device__ int      g_ticket;          // scan tile ticket   (reset by final)
__device__ int      g_qticket;         // query work ticket  (reset by final)
__device__ unsigned g_tstate[NTILE];   // lookback states    (reset by final)
__device__ float    g_cpart[NCHUNK2];  // per-chunk partial sums (16 queries)

// ---------------------------------------------------------------------------
// Pack points, compute cells, histogram.
// t in [0,131072): slot = t>>13 (b*2 + side), i = t&8191. side0=x, side1=y.
// ---------------------------------------------------------------------------
__global__ void assign_kernel(const float* __restrict__ x,
                              const float* __restrict__ y) {
    int t = blockIdx.x * 256 + threadIdx.x;
    int slot = t >> 13, i = t & (NPTS - 1);
    int b = slot >> 1;
    const float* src = (slot & 1) ? y : x;
    const float* p = src + ((size_t)b * NPTS + i) * 3;
    float px = p[0], py = p[1], pz = p[2];
    int cx = min(G - 1, max(0, (int)((px - LOB) * INVH)));
    int cy = min(G - 1, max(0, (int)((py - LOB) * INVH)));
    int cz = min(G - 1, max(0, (int)((pz - LOB) * INVH)));
    int c = slot * NC + ((cz * G + cy) * G + cx);
    g_pk[t] = make_float4(px, py, pz, 0.0f);
    g_cell[t] = c;
    atomicAdd(&g_cnt[c], 1);
}

// ---------------------------------------------------------------------------
// Single-pass exclusive scan of g_cnt (decoupled lookback, ticket-ordered).
// Zeroes g_cnt for the next graph replay; fills g_start and g_cursor.
// ---------------------------------------------------------------------------
__global__ void __launch_bounds__(1024) scan_kernel() {
    __shared__ int tile_s, exc_s;
    __shared__ int ws[32];
    int tid = threadIdx.x, lane = tid & 31, w = tid >> 5;

    if (tid == 0) tile_s = atomicAdd(&g_ticket, 1);
    __syncthreads();
    const int tile = tile_s;
    const int i = tile * 1024 + tid;

    int v = g_cnt[i];
    g_cnt[i] = 0;                                  // self-clean for next call

    int s = v;
    #pragma unroll
    for (int o = 1; o < 32; o <<= 1) {
        int t = __shfl_up_sync(0xffffffffu, s, o);
        if (lane >= o) s += t;
    }
    if (lane == 31) ws[w] = s;
    __syncthreads();
    if (w == 0) {
        int t = ws[lane];
        #pragma unroll
        for (int o = 1; o < 32; o <<= 1) {
            int u = __shfl_up_sync(0xffffffffu, t, o);
            if (lane >= o) t += u;
        }
        ws[lane] = t;
    }
    __syncthreads();
    int local_exc = ((w > 0) ? ws[w - 1] : 0) + s - v;
    int total = ws[31];

    if (tid == 0) {
        if (tile == 0) {
            __threadfence();
            atomicExch(&g_tstate[0], FLG_INC | (unsigned)total);
            exc_s = 0;
        } else {
            __threadfence();
            atomicExch(&g_tstate[tile], FLG_AGG | (unsigned)total);
            int exc = 0, j = tile - 1;
            while (true) {
                unsigned st = atomicAdd(&g_tstate[j], 0u);
                if (st & FLG_INC) { exc += (int)(st & VALMASK); break; }
                if (st & FLG_AGG) { exc += (int)(st & VALMASK); j--; }
            }
            __threadfence();
            atomicExch(&g_tstate[tile], FLG_INC | (unsigned)(exc + total));
            exc_s = exc;
        }
    }
    __syncthreads();
    int e = exc_s + local_exc;
    g_start[i]  = e;
    g_cursor[i] = e;
    if (i == 0) g_start[NCT] = TOTPTS;
}

__global__ void scatter_kernel() {
    int t = blockIdx.x * 256 + threadIdx.x;
    int pos = atomicAdd(&g_cursor[g_cell[t]], 1);
    g_sorted[pos] = g_pk[t];
}

// ---------------------------------------------------------------------------
// Scan candidates [s,e) taking every 2nd element starting at `sub` (the two
// lanes of a pair cover the full range between them).
// ---------------------------------------------------------------------------
__device__ __forceinline__ void scan2(int s, int e, int sub, float4 qp,
                                      float& best) {
    for (int j = s + sub; j < e; j += 2) {
        float4 p = g_sorted[j];
        float dx = qp.x - p.x, dy = qp.y - p.y, dz = qp.z - p.z;
        best = fminf(best, fmaf(dx, dx, fmaf(dy, dy, dz * dz)));
    }
}

// ---------------------------------------------------------------------------
// Exact NN via expanding Chebyshev shells over the CSR grid.
// - Warp WORK-STEALING: each warp grabs 16-query chunks from a global ticket.
//   FCFS ticket order ~= identity order -> spatial locality preserved, tail
//   dynamically balanced.
// - 2 LANES PER QUERY: lane pair splits every candidate range (even/odd) and
//   combines with a PAIR-MASKED shfl_xor. The pair mask (3u << (lane&30)) is
//   the fix for R13's deadlock: the while condition is uniform within a pair
//   but divergent across pairs, so full-warp-mask shuffles inside the loop
//   hang; pair-mask shuffles only require the 2 convergent pair lanes.
// - DETERMINISTIC: chunk partials stored per chunk in fixed lane order,
//   independent of which warp processed the chunk.
// Correctness: after ball r is scanned, any unscanned point is >= r*HCELL
// away (per-axis clamped assignment is 1-Lipschitz); stop when
// best <= (r*h)^2; worst case r=G => full scan => exact.
// ---------------------------------------------------------------------------
__global__ void __launch_bounds__(256) query_kernel() {
    const int lane = threadIdx.x & 31;
    const int sub  = lane & 1;                     // position within pair
    const int pair = lane >> 1;                    // query index in chunk
    const unsigned pmask = 3u << (lane & 30);      // pair-local shfl mask

    while (true) {
        int c = 0;
        if (lane == 0) c = atomicAdd(&g_qticket, 1);
        c = __shfl_sync(0xffffffffu, c, 0);
        if (c >= NCHUNK2) break;

        int qid = c * 16 + pair;                   // [0, 131072)
        int d = qid >> 16;
        int q = qid & 65535;
        int b = q >> 13;
        int i = q & (NPTS - 1);
        int qslot  = b * 2 + d;
        int dbslot = b * 2 + (1 - d);

        float4 qp = g_sorted[qslot * NPTS + i];    // cell-sorted query
        int cx = min(G - 1, max(0, (int)((qp.x - LOB) * INVH)));
        int cy = min(G - 1, max(0, (int)((qp.y - LOB) * INVH)));
        int cz = min(G - 1, max(0, (int)((qp.z - LOB) * INVH)));
        const int base = dbslot * NC;

        float best = 1e30f;

        // Ball r=1: 9 x-rows of up to 3 contiguous cells
        const int x0 = max(cx - 1, 0), x1 = min(cx + 1, G - 1);
        #pragma unroll
        for (int k = 0; k < 9; k++) {
            int z = cz + (k / 3) - 1;
            int y = cy + (k % 3) - 1;
            if (((unsigned)z < G) & ((unsigned)y < G)) {
                int row = base + (z * G + y) * G;
                scan2(g_start[row + x0], g_start[row + x1 + 1], sub, qp, best);
            }
        }
        best = fminf(best, __shfl_xor_sync(pmask, best, 1));

        // Expanding shells (rare path; pair lanes stay convergent)
        int r = 1;
        while (!(best <= (r * HCELL) * (r * HCELL) * 0.9999f) && r < G) {
            r++;
            for (int dz = -r; dz <= r; dz++) {
                int z = cz + dz;
                if ((unsigned)z >= G) continue;
                int adz = (dz < 0) ? -dz : dz;
                for (int dy = -r; dy <= r; dy++) {
                    int y = cy + dy;
                    if ((unsigned)y >= G) continue;
                    int ady = (dy < 0) ? -dy : dy;
                    int rowbase = base + (z * G + y) * G;
                    if (adz == r || ady == r) {
                        int xa = max(cx - r, 0), xb = min(cx + r, G - 1);
                        scan2(g_start[rowbase + xa], g_start[rowbase + xb + 1],
                              sub, qp, best);
                    } else {
                        int xa = cx - r;
                        if (xa >= 0)
                            scan2(g_start[rowbase + xa],
                                  g_start[rowbase + xa + 1], sub, qp, best);
                        int xb = cx + r;
                        if (xb < G)
                            scan2(g_start[rowbase + xb],
                                  g_start[rowbase + xb + 1], sub, qp, best);
                    }
                }
            }
            best = fminf(best, __shfl_xor_sync(pmask, best, 1));
        }

        // Deterministic chunk sum: all 32 lanes reconverge here (each pair's
        // loop terminates), so the full-mask tree reduction is legal.
        float v = (sub == 0) ? sqrtf(best + EPSF) : 0.0f;
        #pragma unroll
        for (int o = 16; o > 0; o >>= 1)
            v += __shfl_down_sync(0xffffffffu, v, o);
        if (lane == 0) g_cpart[c] = v;
    }
}

// ---------------------------------------------------------------------------
// Fold 8192 chunk-partials -> 16 (d,b) sums -> max over d -> mean -> total.
// Chunk c covers qids [c*16, c*16+16) => group = c >> 9 (512 chunks/group).
// Also resets scan + query tickets/states for the next graph replay.
// ---------------------------------------------------------------------------
__global__ void __launch_bounds__(512) final_kernel(float* __restrict__ out) {
    int t = threadIdx.x, grp = t >> 5, lane = t & 31;
    g_tstate[t] = 0u;
    if (t == 0) { g_ticket = 0; g_qticket = 0; }

    float s = 0.0f;
    #pragma unroll
    for (int k = 0; k < 16; k++)
        s += g_cpart[grp * 512 + k * 32 + lane];
    #pragma unroll
    for (int o = 16; o > 0; o >>= 1)
        s += __shfl_down_sync(0xffffffffu, s, o);

    __shared__ float ss[16];
    if (lane == 0) ss[grp] = s;
    __syncthreads();
    if (t == 0) {
        float tot = 0.0f;
        #pragma unroll
        for (int bb = 0; bb < BATCH; bb++)
            tot += fmaxf(ss[bb], ss[8 + bb]) * (1.0f / NPTS);
        out[0] = tot;
    }
}

// ---------------------------------------------------------------------------
extern "C" void kernel_launch(void* const* d_in, const int* in_sizes, int n_in,
                              void* d_out, int out_size) {
    const float* x = (const float*)d_in[0];
    const float* y = (const float*)d_in[1];
    float* out = (float*)d_out;

    assign_kernel<<<TOTPTS / 256, 256>>>(x, y);
    scan_kernel<<<NTILE, 1024>>>();
    scatter_kernel<<<TOTPTS / 256, 256>>>();
    query_kernel<<<QGRID, 256>>>();
    final_kernel<<<1, 512>>>(out);
}